// round 2
// baseline (speedup 1.0000x reference)
#include <cuda_runtime.h>
#include <math.h>
#include <stdint.h>

#define NN    100000
#define NE    1600000
#define ETOT  (NE + NN)
#define NG    64
#define CATC  128
#define NHEAD 4
#define OUTD  64
#define EPSN  1e-5f
#define SLOPE 0.2f

// ---------------- scratch (device globals; no allocation allowed) ----------------
__device__ float g_bufX[NN * CATC];   // current node features (layer in/out)
__device__ float g_bufH[NN * CATC];   // GAT-transformed features h = X @ W^T
__device__ float g_agg[NN * CATC];    // sum_e h[src]*p  accumulator
__device__ float g_ssrc[NN * NHEAD];
__device__ float g_sdst[NN * NHEAD];
__device__ float g_m[NN * NHEAD];     // segment max per (dst, head)
__device__ float g_den[NN * NHEAD];   // segment sum of p per (dst, head)
__device__ float g_mean[NG * CATC];
__device__ float g_inv[NG * CATC];
__device__ float g_pool[NG * CATC];
__device__ int   g_start[NG + 2];     // graph start offsets (batch is sorted)

__device__ __forceinline__ float lrelu(float x) { return x > 0.f ? x : SLOPE * x; }
__device__ __forceinline__ float eluf(float x)  { return x > 0.f ? x : __expf(x) - 1.f; }

__device__ __forceinline__ void atomicMaxF(float* a, float v) {
    // order-preserving trick; g_m initialized to -inf
    if (v >= 0.f) atomicMax((int*)a, __float_as_int(v));
    else          atomicMin((unsigned int*)a, __float_as_uint(v));
}

__device__ __forceinline__ void redAdd4(float* addr, float4 v) {
    asm volatile("red.global.add.v4.f32 [%0], {%1,%2,%3,%4};"
                 :: "l"(addr), "f"(v.x), "f"(v.y), "f"(v.z), "f"(v.w) : "memory");
}

// ---------------- GEMM: O[n,o] = sum_k A[n,k] * W[o,k] (+bias) ----------------
// A: [NN,128], W: [128,128] row-major (out-major). BM=64, 256 thr, TM=4, TN=8.
// Full W in smem ws[o][k] (pad 132), A k-chunked 16.
#define GEMM_SMEM ((128 * 132 + 64 * 20) * 4)

template <int ASEL, int DSEL, bool BIAS>
__global__ void k_gemm(const float* __restrict__ Aext,
                       const float* __restrict__ W,
                       const float* __restrict__ bias) {
    extern __shared__ float smem[];
    float (*ws)[132] = (float(*)[132])smem;
    float (*as)[20]  = (float(*)[20])(smem + 128 * 132);

    const float* A = (ASEL == 0) ? Aext : g_bufX;
    float* O       = (DSEL == 0) ? g_bufX : g_bufH;

    int tid = threadIdx.x;
    // load all of W (4096 float4)
    for (int i = tid; i < 128 * 32; i += 256) {
        float4 v = ((const float4*)W)[i];
        int o = i >> 5, kq = (i & 31) * 4;
        ws[o][kq] = v.x; ws[o][kq + 1] = v.y; ws[o][kq + 2] = v.z; ws[o][kq + 3] = v.w;
    }
    int row0 = blockIdx.x * 64;
    int ty = tid >> 4, tx = tid & 15;

    float acc[4][8];
#pragma unroll
    for (int i = 0; i < 4; i++)
#pragma unroll
        for (int j = 0; j < 8; j++) acc[i][j] = 0.f;

    for (int k0 = 0; k0 < 128; k0 += 16) {
        int r = tid >> 2, q = tid & 3;
        int grow = row0 + r;
        float4 v = make_float4(0.f, 0.f, 0.f, 0.f);
        if (grow < NN) v = ((const float4*)A)[grow * 32 + (k0 >> 2) + q];
        as[r][q * 4] = v.x; as[r][q * 4 + 1] = v.y; as[r][q * 4 + 2] = v.z; as[r][q * 4 + 3] = v.w;
        __syncthreads();
#pragma unroll
        for (int kk = 0; kk < 16; kk += 4) {
            float4 a4[4], w4[8];
#pragma unroll
            for (int i = 0; i < 4; i++) a4[i] = *(const float4*)&as[ty * 4 + i][kk];
#pragma unroll
            for (int j = 0; j < 8; j++) w4[j] = *(const float4*)&ws[tx + 16 * j][k0 + kk];
#pragma unroll
            for (int i = 0; i < 4; i++)
#pragma unroll
                for (int j = 0; j < 8; j++) {
                    acc[i][j] += a4[i].x * w4[j].x;
                    acc[i][j] += a4[i].y * w4[j].y;
                    acc[i][j] += a4[i].z * w4[j].z;
                    acc[i][j] += a4[i].w * w4[j].w;
                }
        }
        __syncthreads();
    }
#pragma unroll
    for (int i = 0; i < 4; i++) {
        int grow = row0 + ty * 4 + i;
        if (grow < NN) {
#pragma unroll
            for (int j = 0; j < 8; j++) {
                int c = tx + 16 * j;
                float v = acc[i][j];
                if (BIAS) v += bias[c];
                O[grow * CATC + c] = v;
            }
        }
    }
}

// ---------------- per-node attention scores (warp per node) ----------------
__global__ void k_scores(const float* __restrict__ a_src, const float* __restrict__ a_dst) {
    int w = (blockIdx.x * blockDim.x + threadIdx.x) >> 5;
    int lane = threadIdx.x & 31;
    if (w >= NN) return;
    float4 hv = ((const float4*)g_bufH)[w * 32 + lane];
    float4 as = ((const float4*)a_src)[lane];
    float4 ad = ((const float4*)a_dst)[lane];
    float ps = hv.x * as.x + hv.y * as.y + hv.z * as.z + hv.w * as.w;
    float pd = hv.x * ad.x + hv.y * ad.y + hv.z * ad.z + hv.w * ad.w;
#pragma unroll
    for (int off = 4; off >= 1; off >>= 1) {
        ps += __shfl_xor_sync(0xffffffffu, ps, off);
        pd += __shfl_xor_sync(0xffffffffu, pd, off);
    }
    if ((lane & 7) == 0) {
        int head = lane >> 3;
        g_ssrc[w * 4 + head] = ps;
        g_sdst[w * 4 + head] = pd;
    }
}

// ---------------- init accumulators ----------------
__global__ void k_init() {
    int i = blockIdx.x * blockDim.x + threadIdx.x;
    if (i < NN * CATC) g_agg[i] = 0.f;
    if (i < NN * NHEAD) { g_m[i] = __int_as_float(0xff800000u); g_den[i] = 0.f; }
}

// ---------------- edge pass 1: segment max ----------------
__global__ void k_edge_max(const int* __restrict__ ei) {
    int e = blockIdx.x * blockDim.x + threadIdx.x;
    if (e >= ETOT) return;
    int src, dst;
    if (e < NE) { src = ei[e]; dst = ei[NE + e]; }
    else        { src = dst = e - NE; }
    float4 a = ((const float4*)g_ssrc)[src];
    float4 b = ((const float4*)g_sdst)[dst];
    float* mp = &g_m[dst * 4];
    atomicMaxF(mp + 0, lrelu(a.x + b.x));
    atomicMaxF(mp + 1, lrelu(a.y + b.y));
    atomicMaxF(mp + 2, lrelu(a.z + b.z));
    atomicMaxF(mp + 3, lrelu(a.w + b.w));
}

// ---------------- edge pass 2: exp / denom / weighted scatter (warp per edge) ----------------
__global__ void k_edge_sum(const int* __restrict__ ei) {
    long long gt = (long long)blockIdx.x * blockDim.x + threadIdx.x;
    int e = (int)(gt >> 5);
    if (e >= ETOT) return;
    int lane = threadIdx.x & 31;
    int src, dst;
    if (e < NE) { src = ei[e]; dst = ei[NE + e]; }
    else        { src = dst = e - NE; }
    int head = lane >> 3;
    float s = g_ssrc[src * 4 + head] + g_sdst[dst * 4 + head];
    float p = __expf(lrelu(s) - g_m[dst * 4 + head]);
    if ((lane & 7) == 0) atomicAdd(&g_den[dst * 4 + head], p);
    float4 hv = ((const float4*)g_bufH)[src * 32 + lane];
    float4 v = make_float4(hv.x * p, hv.y * p, hv.z * p, hv.w * p);
    redAdd4(&g_agg[dst * CATC + lane * 4], v);
}

// ---------------- finalize GAT: out = elu(agg/denom + bias) -> g_bufX ----------------
__global__ void k_finalize(const float* __restrict__ bias) {
    int i = blockIdx.x * blockDim.x + threadIdx.x;  // float4 index
    if (i >= NN * 32) return;
    int n = i >> 5, c4 = i & 31, head = c4 >> 3;
    float inv = 1.f / g_den[n * 4 + head];
    float4 v = ((const float4*)g_agg)[i];
    float4 b = ((const float4*)bias)[c4];
    v.x = eluf(v.x * inv + b.x);
    v.y = eluf(v.y * inv + b.y);
    v.z = eluf(v.z * inv + b.z);
    v.w = eluf(v.w * inv + b.w);
    ((float4*)g_bufX)[i] = v;
}

// ---------------- graph segment offsets (batch sorted) ----------------
__global__ void k_start_init() {
    int g = threadIdx.x;
    if (g <= NG) g_start[g] = NN;
}
__global__ void k_start_fill(const int* __restrict__ batch) {
    int i = blockIdx.x * blockDim.x + threadIdx.x;
    if (i >= NN) return;
    int b = batch[i];
    int bp = (i == 0) ? -1 : batch[i - 1];
    for (int g = bp + 1; g <= b; ++g) g_start[g] = i;
}

// ---------------- GraphNorm stats: grid (G, 4 channel-quarters) ----------------
__global__ void k_norm_stats(const float* __restrict__ nms) {
    __shared__ float sh[256], sh2[256];
    int g = blockIdx.x, q = blockIdx.y;
    int tc = threadIdx.x & 31, tr = threadIdx.x >> 5;
    int c = q * 32 + tc;
    int s0 = g_start[g], s1 = g_start[g + 1];
    float s = 0.f, s2 = 0.f;
    for (int r = s0 + tr; r < s1; r += 8) {
        float v = g_bufX[r * CATC + c];
        s += v; s2 += v * v;
    }
    sh[threadIdx.x] = s; sh2[threadIdx.x] = s2;
    __syncthreads();
    for (int off = 128; off >= 32; off >>= 1) {
        if (threadIdx.x < off) {
            sh[threadIdx.x] += sh[threadIdx.x + off];
            sh2[threadIdx.x] += sh2[threadIdx.x + off];
        }
        __syncthreads();
    }
    if (threadIdx.x < 32) {
        int cnt = s1 - s0;
        float mean = 0.f, inv = 0.f;
        if (cnt > 0) {
            float fc = (float)cnt;
            mean = sh[tc] / fc;
            float ms = nms[c];
            float var = sh2[tc] / fc - (2.f * ms - ms * ms) * mean * mean;
            inv = rsqrtf(var + EPSN);
        }
        g_mean[g * CATC + c] = mean;
        g_inv[g * CATC + c] = inv;
    }
}

__global__ void k_norm_apply(const int* __restrict__ batch,
                             const float* __restrict__ w, const float* __restrict__ b,
                             const float* __restrict__ nms) {
    int i = blockIdx.x * blockDim.x + threadIdx.x;  // float4 index
    if (i >= NN * 32) return;
    int n = i >> 5, c4 = i & 31;
    int g = batch[n];
    float4 v  = ((const float4*)g_bufX)[i];
    float4 mn = ((const float4*)g_mean)[g * 32 + c4];
    float4 iv = ((const float4*)g_inv)[g * 32 + c4];
    float4 wv = ((const float4*)w)[c4];
    float4 bv = ((const float4*)b)[c4];
    float4 mv = ((const float4*)nms)[c4];
    v.x = wv.x * (v.x - mv.x * mn.x) * iv.x + bv.x;
    v.y = wv.y * (v.y - mv.y * mn.y) * iv.y + bv.y;
    v.z = wv.z * (v.z - mv.z * mn.z) * iv.z + bv.z;
    v.w = wv.w * (v.w - mv.w * mn.w) * iv.w + bv.w;
    ((float4*)g_bufX)[i] = v;
}

// ---------------- global max pool: grid (G, 4) ----------------
__global__ void k_pool() {
    __shared__ float sh[256];
    int g = blockIdx.x, q = blockIdx.y;
    int tc = threadIdx.x & 31, tr = threadIdx.x >> 5;
    int c = q * 32 + tc;
    int s0 = g_start[g], s1 = g_start[g + 1];
    float m = __int_as_float(0xff800000u);
    for (int r = s0 + tr; r < s1; r += 8)
        m = fmaxf(m, g_bufX[r * CATC + c]);
    sh[threadIdx.x] = m;
    __syncthreads();
    for (int off = 128; off >= 32; off >>= 1) {
        if (threadIdx.x < off) sh[threadIdx.x] = fmaxf(sh[threadIdx.x], sh[threadIdx.x + off]);
        __syncthreads();
    }
    if (threadIdx.x < 32) g_pool[g * CATC + c] = sh[tc];
}

// ---------------- final fc: [G,128] @ [128,64]^T + b ----------------
__global__ void k_fc(const float* __restrict__ fw, const float* __restrict__ fb,
                     float* __restrict__ out) {
    int g = blockIdx.x, o = threadIdx.x;
    float acc = fb[o];
#pragma unroll
    for (int c = 0; c < CATC; c += 4) {
        float4 p  = *(const float4*)&g_pool[g * CATC + c];
        float4 wv = *(const float4*)&fw[o * CATC + c];
        acc += p.x * wv.x + p.y * wv.y + p.z * wv.z + p.w * wv.w;
    }
    out[g * OUTD + o] = acc;
}

// ---------------- launch ----------------
extern "C" void kernel_launch(void* const* d_in, const int* in_sizes, int n_in,
                              void* d_out, int out_size) {
    const float* x     = (const float*)d_in[0];
    const int*   ei    = (const int*)d_in[1];
    const int*   batch = (const int*)d_in[2];
    const float* enc_w = (const float*)d_in[3];
    const float* enc_b = (const float*)d_in[4];
    const float* w1    = (const float*)d_in[5];
    const float* as1   = (const float*)d_in[6];
    const float* ad1   = (const float*)d_in[7];
    const float* b1    = (const float*)d_in[8];
    const float* n1w   = (const float*)d_in[9];
    const float* n1b   = (const float*)d_in[10];
    const float* n1ms  = (const float*)d_in[11];
    const float* w2    = (const float*)d_in[12];
    const float* as2   = (const float*)d_in[13];
    const float* ad2   = (const float*)d_in[14];
    const float* b2    = (const float*)d_in[15];
    const float* n2w   = (const float*)d_in[16];
    const float* n2b   = (const float*)d_in[17];
    const float* n2ms  = (const float*)d_in[18];
    const float* fw    = (const float*)d_in[19];
    const float* fb    = (const float*)d_in[20];
    float* out = (float*)d_out;

    cudaFuncSetAttribute(k_gemm<0, 0, true>,
                         cudaFuncAttributeMaxDynamicSharedMemorySize, GEMM_SMEM);
    cudaFuncSetAttribute(k_gemm<1, 1, false>,
                         cudaFuncAttributeMaxDynamicSharedMemorySize, GEMM_SMEM);

    const int gemmBlocks = (NN + 63) / 64;
    const int elemBlocks = (NN * 32 + 255) / 256;          // float4-elementwise over [N,128]
    const int initBlocks = (NN * CATC + 255) / 256;
    const int emaxBlocks = (ETOT + 255) / 256;
    const int esumBlocks = (int)(((long long)ETOT * 32 + 255) / 256);

    k_start_init<<<1, NG + 1>>>();
    k_start_fill<<<(NN + 255) / 256, 256>>>(batch);

    // encoder
    k_gemm<0, 0, true><<<gemmBlocks, 256, GEMM_SMEM>>>(x, enc_w, enc_b);

    // ---- layer 1 ----
    k_gemm<1, 1, false><<<gemmBlocks, 256, GEMM_SMEM>>>(nullptr, w1, nullptr);
    k_scores<<<(NN * 32 + 255) / 256, 256>>>(as1, ad1);
    k_init<<<initBlocks, 256>>>();
    k_edge_max<<<emaxBlocks, 256>>>(ei);
    k_edge_sum<<<esumBlocks, 256>>>(ei);
    k_finalize<<<elemBlocks, 256>>>(b1);
    k_norm_stats<<<dim3(NG, 4), 256>>>(n1ms);
    k_norm_apply<<<elemBlocks, 256>>>(batch, n1w, n1b, n1ms);

    // ---- layer 2 ----
    k_gemm<1, 1, false><<<gemmBlocks, 256, GEMM_SMEM>>>(nullptr, w2, nullptr);
    k_scores<<<(NN * 32 + 255) / 256, 256>>>(as2, ad2);
    k_init<<<initBlocks, 256>>>();
    k_edge_max<<<emaxBlocks, 256>>>(ei);
    k_edge_sum<<<esumBlocks, 256>>>(ei);
    k_finalize<<<elemBlocks, 256>>>(b2);
    k_norm_stats<<<dim3(NG, 4), 256>>>(n2ms);
    k_norm_apply<<<elemBlocks, 256>>>(batch, n2w, n2b, n2ms);

    // ---- pool + fc ----
    k_pool<<<dim3(NG, 4), 256>>>();
    k_fc<<<NG, OUTD>>>(fw, fb, out);
}

// round 3
// speedup vs baseline: 1.0713x; 1.0713x over previous
#include <cuda_runtime.h>
#include <math.h>
#include <stdint.h>

#define NN    100000
#define NE    1600000
#define ETOT  (NE + NN)
#define NG    64
#define CATC  128
#define NHEAD 4
#define OUTD  64
#define EPSN  1e-5f
#define SLOPE 0.2f

// ---------------- scratch (device globals) ----------------
__device__ float g_bufX[NN * CATC];
__device__ float g_bufH[NN * CATC];
__device__ float g_agg[NN * CATC];
__device__ float g_ssrc[NN * NHEAD];
__device__ float g_sdst[NN * NHEAD];
__device__ float g_den[NN * NHEAD];
__device__ float g_maxs[NHEAD];
__device__ float g_maxd[NHEAD];
__device__ float g_shift[NHEAD];
__device__ float g_mean[NG * CATC];
__device__ float g_inv[NG * CATC];
__device__ float g_pool[NG * CATC];
__device__ int   g_start[NG + 2];

__device__ __forceinline__ float lrelu(float x) { return x > 0.f ? x : SLOPE * x; }
__device__ __forceinline__ float eluf(float x)  { return x > 0.f ? x : __expf(x) - 1.f; }

__device__ __forceinline__ void atomicMaxF(float* a, float v) {
    if (v >= 0.f) atomicMax((int*)a, __float_as_int(v));
    else          atomicMin((unsigned int*)a, __float_as_uint(v));
}

__device__ __forceinline__ void redAdd4(float* addr, float4 v) {
    asm volatile("red.global.add.v4.f32 [%0], {%1,%2,%3,%4};"
                 :: "l"(addr), "f"(v.x), "f"(v.y), "f"(v.z), "f"(v.w) : "memory");
}

// ---------------- GEMM v2: O[n,c] = sum_k A[n,k]*W[c,k] (+bias) (+score epilogue) ----
// BM=128, BN=128 (full), BK=32, 256 threads, TM=8, TN=8.
// smem k-major: ws[k][c] (full K), as[kk][r] per chunk -> LDS.128 on both operands.
#define GEMM_SMEM ((128 * 132 + 32 * 132) * 4)

template <int ASEL, int DSEL, bool BIAS, bool SCORES>
__global__ void k_gemm(const float* __restrict__ Aext,
                       const float* __restrict__ W,
                       const float* __restrict__ bias,
                       const float* __restrict__ a_src,
                       const float* __restrict__ a_dst) {
    extern __shared__ float smem[];
    float (*ws)[132] = (float(*)[132])smem;                 // [128][132]  ws[k][c]
    float (*as)[132] = (float(*)[132])(smem + 128 * 132);   // [32][132]   as[kk][r]

    const float* A = (ASEL == 0) ? Aext : g_bufX;
    float* O       = (DSEL == 0) ? g_bufX : g_bufH;

    int tid = threadIdx.x;
    int ty = tid >> 4, tx = tid & 15;
    int row0 = blockIdx.x * 128;

    // load W transposed into ws[k][c]
    for (int i = tid; i < 128 * 32; i += 256) {
        float4 v = ((const float4*)W)[i];
        int c = i >> 5, q = i & 31;
        ws[4 * q + 0][c] = v.x; ws[4 * q + 1][c] = v.y;
        ws[4 * q + 2][c] = v.z; ws[4 * q + 3][c] = v.w;
    }

    float acc[8][8];
#pragma unroll
    for (int i = 0; i < 8; i++)
#pragma unroll
        for (int j = 0; j < 8; j++) acc[i][j] = 0.f;

    for (int k0 = 0; k0 < 128; k0 += 32) {
        // load A chunk transposed: as[kk][r] = A[row0+r][k0+kk]
#pragma unroll
        for (int it = 0; it < 4; it++) {
            int idx = tid + 256 * it;          // 0..1023
            int r = idx >> 3, q = idx & 7;
            int grow = row0 + r;
            float4 v = make_float4(0.f, 0.f, 0.f, 0.f);
            if (grow < NN) v = ((const float4*)A)[grow * 32 + (k0 >> 2) + q];
            as[4 * q + 0][r] = v.x; as[4 * q + 1][r] = v.y;
            as[4 * q + 2][r] = v.z; as[4 * q + 3][r] = v.w;
        }
        __syncthreads();
#pragma unroll
        for (int kk = 0; kk < 32; kk++) {
            float4 a0 = *(const float4*)&as[kk][ty * 8];
            float4 a1 = *(const float4*)&as[kk][ty * 8 + 4];
            float4 w0 = *(const float4*)&ws[k0 + kk][tx * 8];
            float4 w1 = *(const float4*)&ws[k0 + kk][tx * 8 + 4];
            float av[8] = {a0.x, a0.y, a0.z, a0.w, a1.x, a1.y, a1.z, a1.w};
            float wv[8] = {w0.x, w0.y, w0.z, w0.w, w1.x, w1.y, w1.z, w1.w};
#pragma unroll
            for (int i = 0; i < 8; i++)
#pragma unroll
                for (int j = 0; j < 8; j++)
                    acc[i][j] += av[i] * wv[j];
        }
        __syncthreads();
    }

    // optional bias (columns tx*8..tx*8+7)
    float bv[8];
    if (BIAS) {
        float4 b0 = ((const float4*)bias)[tx * 2];
        float4 b1 = ((const float4*)bias)[tx * 2 + 1];
        bv[0] = b0.x; bv[1] = b0.y; bv[2] = b0.z; bv[3] = b0.w;
        bv[4] = b1.x; bv[5] = b1.y; bv[6] = b1.z; bv[7] = b1.w;
    }

    // store O
#pragma unroll
    for (int i = 0; i < 8; i++) {
        int grow = row0 + ty * 8 + i;
        if (grow < NN) {
            float4 o0, o1;
            o0.x = acc[i][0]; o0.y = acc[i][1]; o0.z = acc[i][2]; o0.w = acc[i][3];
            o1.x = acc[i][4]; o1.y = acc[i][5]; o1.z = acc[i][6]; o1.w = acc[i][7];
            if (BIAS) {
                o0.x += bv[0]; o0.y += bv[1]; o0.z += bv[2]; o0.w += bv[3];
                o1.x += bv[4]; o1.y += bv[5]; o1.z += bv[6]; o1.w += bv[7];
            }
            float4* op = (float4*)&O[grow * CATC + tx * 8];
            op[0] = o0; op[1] = o1;
        }
    }

    // fused attention-score epilogue: s_src/s_dst per (row, head)
    if (SCORES) {
        float4 s0 = ((const float4*)a_src)[tx * 2];
        float4 s1 = ((const float4*)a_src)[tx * 2 + 1];
        float4 d0 = ((const float4*)a_dst)[tx * 2];
        float4 d1 = ((const float4*)a_dst)[tx * 2 + 1];
        float sv[8] = {s0.x, s0.y, s0.z, s0.w, s1.x, s1.y, s1.z, s1.w};
        float dv[8] = {d0.x, d0.y, d0.z, d0.w, d1.x, d1.y, d1.z, d1.w};
        int head = tx >> 2;
#pragma unroll
        for (int i = 0; i < 8; i++) {
            float ss = 0.f, sd = 0.f;
#pragma unroll
            for (int j = 0; j < 8; j++) {
                ss += acc[i][j] * sv[j];
                sd += acc[i][j] * dv[j];
            }
            // reduce over the 4 threads (tx%4) covering this head's 32 cols
            ss += __shfl_xor_sync(0xffffffffu, ss, 1);
            ss += __shfl_xor_sync(0xffffffffu, ss, 2);
            sd += __shfl_xor_sync(0xffffffffu, sd, 1);
            sd += __shfl_xor_sync(0xffffffffu, sd, 2);
            int grow = row0 + ty * 8 + i;
            if ((tx & 3) == 0 && grow < NN) {
                g_ssrc[grow * 4 + head] = ss;
                g_sdst[grow * 4 + head] = sd;
            }
        }
    }
}

// ---------------- per-head global max of scores (softmax shift bound) ----------------
__global__ void k_shift_init() {
    if (threadIdx.x < NHEAD) {
        g_maxs[threadIdx.x] = __int_as_float(0xff800000u);
        g_maxd[threadIdx.x] = __int_as_float(0xff800000u);
    }
}
__global__ void k_shift() {
    int i0 = blockIdx.x * blockDim.x + threadIdx.x;
    int stride = gridDim.x * blockDim.x;   // multiple of 4 -> head invariant per thread
    float ms = __int_as_float(0xff800000u);
    float md = ms;
    for (int i = i0; i < NN * NHEAD; i += stride) {
        ms = fmaxf(ms, g_ssrc[i]);
        md = fmaxf(md, g_sdst[i]);
    }
#pragma unroll
    for (int off = 4; off <= 16; off <<= 1) {
        ms = fmaxf(ms, __shfl_xor_sync(0xffffffffu, ms, off));
        md = fmaxf(md, __shfl_xor_sync(0xffffffffu, md, off));
    }
    int lane = threadIdx.x & 31;
    if (lane < 4) {
        atomicMaxF(&g_maxs[lane], ms);
        atomicMaxF(&g_maxd[lane], md);
    }
}

// ---------------- init accumulators (+ combine shift) ----------------
__global__ void k_init() {
    int i = blockIdx.x * blockDim.x + threadIdx.x;
    if (i < NN * CATC) g_agg[i] = 0.f;
    if (i < NN * NHEAD) g_den[i] = 0.f;
    if (i < NHEAD) g_shift[i] = lrelu(g_maxs[i] + g_maxd[i]);
}

// ---------------- edge pass: exp / denom / weighted scatter (warp per edge) --------
__global__ void k_edge_sum(const int* __restrict__ ei) {
    long long gt = (long long)blockIdx.x * blockDim.x + threadIdx.x;
    int e = (int)(gt >> 5);
    if (e >= ETOT) return;
    int lane = threadIdx.x & 31;
    int src, dst;
    if (e < NE) { src = __ldg(&ei[e]); dst = __ldg(&ei[NE + e]); }
    else        { src = dst = e - NE; }
    int head = lane >> 3;
    float s = g_ssrc[src * 4 + head] + g_sdst[dst * 4 + head];
    float p = __expf(lrelu(s) - g_shift[head]);
    if ((lane & 7) == 0) atomicAdd(&g_den[dst * 4 + head], p);
    float4 hv = ((const float4*)g_bufH)[src * 32 + lane];
    float4 v = make_float4(hv.x * p, hv.y * p, hv.z * p, hv.w * p);
    redAdd4(&g_agg[dst * CATC + lane * 4], v);
}

// ---------------- finalize GAT: out = elu(agg/denom + bias) -> g_bufX --------------
__global__ void k_finalize(const float* __restrict__ bias) {
    int i = blockIdx.x * blockDim.x + threadIdx.x;  // float4 index
    if (i >= NN * 32) return;
    int n = i >> 5, c4 = i & 31, head = c4 >> 3;
    float inv = 1.f / g_den[n * 4 + head];
    float4 v = ((const float4*)g_agg)[i];
    float4 b = ((const float4*)bias)[c4];
    v.x = eluf(v.x * inv + b.x);
    v.y = eluf(v.y * inv + b.y);
    v.z = eluf(v.z * inv + b.z);
    v.w = eluf(v.w * inv + b.w);
    ((float4*)g_bufX)[i] = v;
}

// ---------------- graph segment offsets (batch sorted) ----------------
__global__ void k_start_init() {
    int g = threadIdx.x;
    if (g <= NG) g_start[g] = NN;
}
__global__ void k_start_fill(const int* __restrict__ batch) {
    int i = blockIdx.x * blockDim.x + threadIdx.x;
    if (i >= NN) return;
    int b = batch[i];
    int bp = (i == 0) ? -1 : batch[i - 1];
    for (int g = bp + 1; g <= b; ++g) g_start[g] = i;
}

// ---------------- GraphNorm stats: grid (G, 4 channel-quarters) ----------------
__global__ void k_norm_stats(const float* __restrict__ nms) {
    __shared__ float sh[256], sh2[256];
    int g = blockIdx.x, q = blockIdx.y;
    int tc = threadIdx.x & 31, tr = threadIdx.x >> 5;
    int c = q * 32 + tc;
    int s0 = g_start[g], s1 = g_start[g + 1];
    float s = 0.f, s2 = 0.f;
    for (int r = s0 + tr; r < s1; r += 8) {
        float v = g_bufX[r * CATC + c];
        s += v; s2 += v * v;
    }
    sh[threadIdx.x] = s; sh2[threadIdx.x] = s2;
    __syncthreads();
    for (int off = 128; off >= 32; off >>= 1) {
        if (threadIdx.x < off) {
            sh[threadIdx.x] += sh[threadIdx.x + off];
            sh2[threadIdx.x] += sh2[threadIdx.x + off];
        }
        __syncthreads();
    }
    if (threadIdx.x < 32) {
        int cnt = s1 - s0;
        float mean = 0.f, inv = 0.f;
        if (cnt > 0) {
            float fc = (float)cnt;
            mean = sh[tc] / fc;
            float ms = nms[c];
            float var = sh2[tc] / fc - (2.f * ms - ms * ms) * mean * mean;
            inv = rsqrtf(var + EPSN);
        }
        g_mean[g * CATC + c] = mean;
        g_inv[g * CATC + c] = inv;
    }
}

__global__ void k_norm_apply(const int* __restrict__ batch,
                             const float* __restrict__ w, const float* __restrict__ b,
                             const float* __restrict__ nms) {
    int i = blockIdx.x * blockDim.x + threadIdx.x;  // float4 index
    if (i >= NN * 32) return;
    int n = i >> 5, c4 = i & 31;
    int g = batch[n];
    float4 v  = ((const float4*)g_bufX)[i];
    float4 mn = ((const float4*)g_mean)[g * 32 + c4];
    float4 iv = ((const float4*)g_inv)[g * 32 + c4];
    float4 wv = ((const float4*)w)[c4];
    float4 bv = ((const float4*)b)[c4];
    float4 mv = ((const float4*)nms)[c4];
    v.x = wv.x * (v.x - mv.x * mn.x) * iv.x + bv.x;
    v.y = wv.y * (v.y - mv.y * mn.y) * iv.y + bv.y;
    v.z = wv.z * (v.z - mv.z * mn.z) * iv.z + bv.z;
    v.w = wv.w * (v.w - mv.w * mn.w) * iv.w + bv.w;
    ((float4*)g_bufX)[i] = v;
}

// ---------------- global max pool: grid (G, 4) ----------------
__global__ void k_pool() {
    __shared__ float sh[256];
    int g = blockIdx.x, q = blockIdx.y;
    int tc = threadIdx.x & 31, tr = threadIdx.x >> 5;
    int c = q * 32 + tc;
    int s0 = g_start[g], s1 = g_start[g + 1];
    float m = __int_as_float(0xff800000u);
    for (int r = s0 + tr; r < s1; r += 8)
        m = fmaxf(m, g_bufX[r * CATC + c]);
    sh[threadIdx.x] = m;
    __syncthreads();
    for (int off = 128; off >= 32; off >>= 1) {
        if (threadIdx.x < off) sh[threadIdx.x] = fmaxf(sh[threadIdx.x], sh[threadIdx.x + off]);
        __syncthreads();
    }
    if (threadIdx.x < 32) g_pool[g * CATC + c] = sh[tc];
}

// ---------------- final fc: [G,128] @ [128,64]^T + b ----------------
__global__ void k_fc(const float* __restrict__ fw, const float* __restrict__ fb,
                     float* __restrict__ out) {
    int g = blockIdx.x, o = threadIdx.x;
    float acc = fb[o];
#pragma unroll
    for (int c = 0; c < CATC; c += 4) {
        float4 p  = *(const float4*)&g_pool[g * CATC + c];
        float4 wv = *(const float4*)&fw[o * CATC + c];
        acc += p.x * wv.x + p.y * wv.y + p.z * wv.z + p.w * wv.w;
    }
    out[g * OUTD + o] = acc;
}

// ---------------- launch ----------------
extern "C" void kernel_launch(void* const* d_in, const int* in_sizes, int n_in,
                              void* d_out, int out_size) {
    const float* x     = (const float*)d_in[0];
    const int*   ei    = (const int*)d_in[1];
    const int*   batch = (const int*)d_in[2];
    const float* enc_w = (const float*)d_in[3];
    const float* enc_b = (const float*)d_in[4];
    const float* w1    = (const float*)d_in[5];
    const float* as1   = (const float*)d_in[6];
    const float* ad1   = (const float*)d_in[7];
    const float* b1    = (const float*)d_in[8];
    const float* n1w   = (const float*)d_in[9];
    const float* n1b   = (const float*)d_in[10];
    const float* n1ms  = (const float*)d_in[11];
    const float* w2    = (const float*)d_in[12];
    const float* as2   = (const float*)d_in[13];
    const float* ad2   = (const float*)d_in[14];
    const float* b2    = (const float*)d_in[15];
    const float* n2w   = (const float*)d_in[16];
    const float* n2b   = (const float*)d_in[17];
    const float* n2ms  = (const float*)d_in[18];
    const float* fw    = (const float*)d_in[19];
    const float* fb    = (const float*)d_in[20];
    float* out = (float*)d_out;

    cudaFuncSetAttribute(k_gemm<0, 0, true, false>,
                         cudaFuncAttributeMaxDynamicSharedMemorySize, GEMM_SMEM);
    cudaFuncSetAttribute(k_gemm<1, 1, false, true>,
                         cudaFuncAttributeMaxDynamicSharedMemorySize, GEMM_SMEM);

    const int gemmBlocks = (NN + 127) / 128;
    const int elemBlocks = (NN * 32 + 255) / 256;
    const int initBlocks = (NN * CATC + 255) / 256;
    const int esumBlocks = (int)(((long long)ETOT * 32 + 255) / 256);

    k_start_init<<<1, NG + 1>>>();
    k_start_fill<<<(NN + 255) / 256, 256>>>(batch);

    // encoder
    k_gemm<0, 0, true, false><<<gemmBlocks, 256, GEMM_SMEM>>>(x, enc_w, enc_b, nullptr, nullptr);

    // ---- layer 1 ----
    k_gemm<1, 1, false, true><<<gemmBlocks, 256, GEMM_SMEM>>>(nullptr, w1, nullptr, as1, ad1);
    k_shift_init<<<1, 32>>>();
    k_shift<<<296, 256>>>();
    k_init<<<initBlocks, 256>>>();
    k_edge_sum<<<esumBlocks, 256>>>(ei);
    k_finalize<<<elemBlocks, 256>>>(b1);
    k_norm_stats<<<dim3(NG, 4), 256>>>(n1ms);
    k_norm_apply<<<elemBlocks, 256>>>(batch, n1w, n1b, n1ms);

    // ---- layer 2 ----
    k_gemm<1, 1, false, true><<<gemmBlocks, 256, GEMM_SMEM>>>(nullptr, w2, nullptr, as2, ad2);
    k_shift_init<<<1, 32>>>();
    k_shift<<<296, 256>>>();
    k_init<<<initBlocks, 256>>>();
    k_edge_sum<<<esumBlocks, 256>>>(ei);
    k_finalize<<<elemBlocks, 256>>>(b2);
    k_norm_stats<<<dim3(NG, 4), 256>>>(n2ms);
    k_norm_apply<<<elemBlocks, 256>>>(batch, n2w, n2b, n2ms);

    // ---- pool + fc ----
    k_pool<<<dim3(NG, 4), 256>>>();
    k_fc<<<NG, OUTD>>>(fw, fb, out);
}

// round 4
// speedup vs baseline: 1.6561x; 1.5459x over previous
#include <cuda_runtime.h>
#include <math.h>
#include <stdint.h>

#define NN    100000
#define NE    1600000
#define NG    64
#define CATC  128
#define NHEAD 4
#define OUTD  64
#define EPSN  1e-5f
#define SLOPE 0.2f
#define SCAN_B ((NN + 1023) / 1024)   // 98

// ---------------- scratch (device globals) ----------------
__device__ float g_bufX[NN * CATC];
__device__ float g_bufH[NN * CATC];
__device__ float g_ssrc[NN * NHEAD];
__device__ float g_sdst[NN * NHEAD];
__device__ float g_maxs[NHEAD];
__device__ float g_maxd[NHEAD];
__device__ float g_mean[NG * CATC];
__device__ float g_inv[NG * CATC];
__device__ float g_pool[NG * CATC];
__device__ int   g_start[NG + 2];
// CSR (dst-major, real edges only; self-loops handled in-kernel)
__device__ int   g_cnt[NN];
__device__ int   g_off[NN + 1];
__device__ int   g_cursor[NN];
__device__ int   g_bsum[SCAN_B];
__device__ int   g_boff[SCAN_B];
__device__ int   g_csr[NE];

__device__ __forceinline__ float lrelu(float x) { return x > 0.f ? x : SLOPE * x; }
__device__ __forceinline__ float eluf(float x)  { return x > 0.f ? x : __expf(x) - 1.f; }

__device__ __forceinline__ void atomicMaxF(float* a, float v) {
    if (v >= 0.f) atomicMax((int*)a, __float_as_int(v));
    else          atomicMin((unsigned int*)a, __float_as_uint(v));
}

// ---------------- GEMM: O[n,c] = sum_k A[n,k]*W[c,k] (+bias) (+score epilogue) ----
#define GEMM_SMEM ((128 * 132 + 32 * 132) * 4)

template <int ASEL, int DSEL, bool BIAS, bool SCORES>
__global__ void k_gemm(const float* __restrict__ Aext,
                       const float* __restrict__ W,
                       const float* __restrict__ bias,
                       const float* __restrict__ a_src,
                       const float* __restrict__ a_dst) {
    extern __shared__ float smem[];
    float (*ws)[132] = (float(*)[132])smem;                 // ws[k][c]
    float (*as)[132] = (float(*)[132])(smem + 128 * 132);   // as[kk][r]

    const float* A = (ASEL == 0) ? Aext : g_bufX;
    float* O       = (DSEL == 0) ? g_bufX : g_bufH;

    int tid = threadIdx.x;
    int ty = tid >> 4, tx = tid & 15;
    int row0 = blockIdx.x * 128;

    for (int i = tid; i < 128 * 32; i += 256) {
        float4 v = ((const float4*)W)[i];
        int c = i >> 5, q = i & 31;
        ws[4 * q + 0][c] = v.x; ws[4 * q + 1][c] = v.y;
        ws[4 * q + 2][c] = v.z; ws[4 * q + 3][c] = v.w;
    }

    float acc[8][8];
#pragma unroll
    for (int i = 0; i < 8; i++)
#pragma unroll
        for (int j = 0; j < 8; j++) acc[i][j] = 0.f;

    for (int k0 = 0; k0 < 128; k0 += 32) {
#pragma unroll
        for (int it = 0; it < 4; it++) {
            int idx = tid + 256 * it;
            int r = idx >> 3, q = idx & 7;
            int grow = row0 + r;
            float4 v = make_float4(0.f, 0.f, 0.f, 0.f);
            if (grow < NN) v = ((const float4*)A)[grow * 32 + (k0 >> 2) + q];
            as[4 * q + 0][r] = v.x; as[4 * q + 1][r] = v.y;
            as[4 * q + 2][r] = v.z; as[4 * q + 3][r] = v.w;
        }
        __syncthreads();
#pragma unroll
        for (int kk = 0; kk < 32; kk++) {
            float4 a0 = *(const float4*)&as[kk][ty * 8];
            float4 a1 = *(const float4*)&as[kk][ty * 8 + 4];
            float4 w0 = *(const float4*)&ws[k0 + kk][tx * 8];
            float4 w1 = *(const float4*)&ws[k0 + kk][tx * 8 + 4];
            float av[8] = {a0.x, a0.y, a0.z, a0.w, a1.x, a1.y, a1.z, a1.w};
            float wv[8] = {w0.x, w0.y, w0.z, w0.w, w1.x, w1.y, w1.z, w1.w};
#pragma unroll
            for (int i = 0; i < 8; i++)
#pragma unroll
                for (int j = 0; j < 8; j++)
                    acc[i][j] += av[i] * wv[j];
        }
        __syncthreads();
    }

    float bv[8];
    if (BIAS) {
        float4 b0 = ((const float4*)bias)[tx * 2];
        float4 b1 = ((const float4*)bias)[tx * 2 + 1];
        bv[0] = b0.x; bv[1] = b0.y; bv[2] = b0.z; bv[3] = b0.w;
        bv[4] = b1.x; bv[5] = b1.y; bv[6] = b1.z; bv[7] = b1.w;
    }

#pragma unroll
    for (int i = 0; i < 8; i++) {
        int grow = row0 + ty * 8 + i;
        if (grow < NN) {
            float4 o0, o1;
            o0.x = acc[i][0]; o0.y = acc[i][1]; o0.z = acc[i][2]; o0.w = acc[i][3];
            o1.x = acc[i][4]; o1.y = acc[i][5]; o1.z = acc[i][6]; o1.w = acc[i][7];
            if (BIAS) {
                o0.x += bv[0]; o0.y += bv[1]; o0.z += bv[2]; o0.w += bv[3];
                o1.x += bv[4]; o1.y += bv[5]; o1.z += bv[6]; o1.w += bv[7];
            }
            float4* op = (float4*)&O[grow * CATC + tx * 8];
            op[0] = o0; op[1] = o1;
        }
    }

    if (SCORES) {
        float4 s0 = ((const float4*)a_src)[tx * 2];
        float4 s1 = ((const float4*)a_src)[tx * 2 + 1];
        float4 d0 = ((const float4*)a_dst)[tx * 2];
        float4 d1 = ((const float4*)a_dst)[tx * 2 + 1];
        float sv[8] = {s0.x, s0.y, s0.z, s0.w, s1.x, s1.y, s1.z, s1.w};
        float dv[8] = {d0.x, d0.y, d0.z, d0.w, d1.x, d1.y, d1.z, d1.w};
        int head = tx >> 2;
#pragma unroll
        for (int i = 0; i < 8; i++) {
            float ss = 0.f, sd = 0.f;
#pragma unroll
            for (int j = 0; j < 8; j++) {
                ss += acc[i][j] * sv[j];
                sd += acc[i][j] * dv[j];
            }
            ss += __shfl_xor_sync(0xffffffffu, ss, 1);
            ss += __shfl_xor_sync(0xffffffffu, ss, 2);
            sd += __shfl_xor_sync(0xffffffffu, sd, 1);
            sd += __shfl_xor_sync(0xffffffffu, sd, 2);
            int grow = row0 + ty * 8 + i;
            if ((tx & 3) == 0 && grow < NN) {
                g_ssrc[grow * 4 + head] = ss;
                g_sdst[grow * 4 + head] = sd;
            }
        }
    }
}

// ---------------- CSR build (once; shared by both layers) ----------------
__global__ void k_cnt_zero() {
    int i = blockIdx.x * blockDim.x + threadIdx.x;
    if (i < NN) g_cnt[i] = 0;
}
__global__ void k_deg(const int* __restrict__ ei) {
    int e = blockIdx.x * blockDim.x + threadIdx.x;
    if (e < NE) atomicAdd(&g_cnt[ei[NE + e]], 1);
}
__global__ void k_scan1() {
    __shared__ int wsum[8];
    int b = blockIdx.x, t = threadIdx.x;
    int idx0 = b * 1024 + t * 4;
    int v[4];
#pragma unroll
    for (int k = 0; k < 4; k++) v[k] = (idx0 + k < NN) ? g_cnt[idx0 + k] : 0;
    int s = v[0] + v[1] + v[2] + v[3];
    int lane = t & 31, wid = t >> 5;
    int incl = s;
#pragma unroll
    for (int off = 1; off <= 16; off <<= 1) {
        int nv = __shfl_up_sync(0xffffffffu, incl, off);
        if (lane >= off) incl += nv;
    }
    if (lane == 31) wsum[wid] = incl;
    __syncthreads();
    if (t == 0) {
        int r = 0;
#pragma unroll
        for (int w = 0; w < 8; w++) { int x = wsum[w]; wsum[w] = r; r += x; }
    }
    __syncthreads();
    int excl = incl - s + wsum[wid];
    int run = excl;
#pragma unroll
    for (int k = 0; k < 4; k++) {
        if (idx0 + k < NN) g_off[idx0 + k] = run;
        run += v[k];
    }
    if (t == 255) g_bsum[b] = excl + s;
}
__global__ void k_scan2() {
    int r = 0;
    for (int b = 0; b < SCAN_B; b++) { g_boff[b] = r; r += g_bsum[b]; }
    g_off[NN] = r;
}
__global__ void k_scan3() {
    int i = blockIdx.x * blockDim.x + threadIdx.x;
    if (i >= NN) return;
    int o = g_off[i] + g_boff[i >> 10];
    g_off[i] = o;
    g_cursor[i] = o;
}
__global__ void k_fill(const int* __restrict__ ei) {
    int e = blockIdx.x * blockDim.x + threadIdx.x;
    if (e >= NE) return;
    int dst = ei[NE + e];
    int pos = atomicAdd(&g_cursor[dst], 1);
    g_csr[pos] = ei[e];
}

// ---------------- per-head global max of scores (softmax shift bound) ----------------
__global__ void k_shift_init() {
    if (threadIdx.x < NHEAD) {
        g_maxs[threadIdx.x] = __int_as_float(0xff800000u);
        g_maxd[threadIdx.x] = __int_as_float(0xff800000u);
    }
}
__global__ void k_shift() {
    int i0 = blockIdx.x * blockDim.x + threadIdx.x;
    int stride = gridDim.x * blockDim.x;
    float ms = __int_as_float(0xff800000u);
    float md = ms;
    for (int i = i0; i < NN * NHEAD; i += stride) {
        ms = fmaxf(ms, g_ssrc[i]);
        md = fmaxf(md, g_sdst[i]);
    }
#pragma unroll
    for (int off = 4; off <= 16; off <<= 1) {
        ms = fmaxf(ms, __shfl_xor_sync(0xffffffffu, ms, off));
        md = fmaxf(md, __shfl_xor_sync(0xffffffffu, md, off));
    }
    int lane = threadIdx.x & 31;
    if (lane < 4) {
        atomicMaxF(&g_maxs[lane], ms);
        atomicMaxF(&g_maxd[lane], md);
    }
}

// ---------------- fused GAT aggregate + softmax + bias + ELU (warp per dst) -------
__global__ void k_gat(const float* __restrict__ bias) {
    int n = (blockIdx.x * blockDim.x + threadIdx.x) >> 5;
    if (n >= NN) return;
    int lane = threadIdx.x & 31;
    int head = lane >> 3;

    float shift = lrelu(g_maxs[head] + g_maxd[head]);
    float sd = g_sdst[n * 4 + head];

    // self-loop
    float p = __expf(lrelu(g_ssrc[n * 4 + head] + sd) - shift);
    float4 hv = ((const float4*)g_bufH)[n * 32 + lane];
    float ax = hv.x * p, ay = hv.y * p, az = hv.z * p, aw = hv.w * p;
    float den = p;

    int o0 = g_off[n], o1 = g_off[n + 1];
    for (int base = o0; base < o1; base += 32) {
        int id = 0;
        if (base + lane < o1) id = g_csr[base + lane];
        int cnt = min(32, o1 - base);
#pragma unroll 4
        for (int j = 0; j < cnt; j++) {
            int src = __shfl_sync(0xffffffffu, id, j);
            float ss = g_ssrc[src * 4 + head];
            float pe = __expf(lrelu(ss + sd) - shift);
            float4 h = ((const float4*)g_bufH)[src * 32 + lane];
            ax += h.x * pe; ay += h.y * pe; az += h.z * pe; aw += h.w * pe;
            den += pe;
        }
    }
    float inv = 1.f / den;
    float4 b = ((const float4*)bias)[lane];
    float4 o;
    o.x = eluf(ax * inv + b.x);
    o.y = eluf(ay * inv + b.y);
    o.z = eluf(az * inv + b.z);
    o.w = eluf(aw * inv + b.w);
    ((float4*)g_bufX)[n * 32 + lane] = o;
}

// ---------------- graph segment offsets (batch sorted) ----------------
__global__ void k_start_init() {
    int g = threadIdx.x;
    if (g <= NG) g_start[g] = NN;
}
__global__ void k_start_fill(const int* __restrict__ batch) {
    int i = blockIdx.x * blockDim.x + threadIdx.x;
    if (i >= NN) return;
    int b = batch[i];
    int bp = (i == 0) ? -1 : batch[i - 1];
    for (int g = bp + 1; g <= b; ++g) g_start[g] = i;
}

// ---------------- GraphNorm stats: grid (G, 4 channel-quarters) ----------------
__global__ void k_norm_stats(const float* __restrict__ nms) {
    __shared__ float sh[256], sh2[256];
    int g = blockIdx.x, q = blockIdx.y;
    int tc = threadIdx.x & 31, tr = threadIdx.x >> 5;
    int c = q * 32 + tc;
    int s0 = g_start[g], s1 = g_start[g + 1];
    float s = 0.f, s2 = 0.f;
    for (int r = s0 + tr; r < s1; r += 8) {
        float v = g_bufX[r * CATC + c];
        s += v; s2 += v * v;
    }
    sh[threadIdx.x] = s; sh2[threadIdx.x] = s2;
    __syncthreads();
    for (int off = 128; off >= 32; off >>= 1) {
        if (threadIdx.x < off) {
            sh[threadIdx.x] += sh[threadIdx.x + off];
            sh2[threadIdx.x] += sh2[threadIdx.x + off];
        }
        __syncthreads();
    }
    if (threadIdx.x < 32) {
        int cnt = s1 - s0;
        float mean = 0.f, inv = 0.f;
        if (cnt > 0) {
            float fc = (float)cnt;
            mean = sh[tc] / fc;
            float ms = nms[c];
            float var = sh2[tc] / fc - (2.f * ms - ms * ms) * mean * mean;
            inv = rsqrtf(var + EPSN);
        }
        g_mean[g * CATC + c] = mean;
        g_inv[g * CATC + c] = inv;
    }
}

__global__ void k_norm_apply(const int* __restrict__ batch,
                             const float* __restrict__ w, const float* __restrict__ b,
                             const float* __restrict__ nms) {
    int i = blockIdx.x * blockDim.x + threadIdx.x;
    if (i >= NN * 32) return;
    int n = i >> 5, c4 = i & 31;
    int g = batch[n];
    float4 v  = ((const float4*)g_bufX)[i];
    float4 mn = ((const float4*)g_mean)[g * 32 + c4];
    float4 iv = ((const float4*)g_inv)[g * 32 + c4];
    float4 wv = ((const float4*)w)[c4];
    float4 bv = ((const float4*)b)[c4];
    float4 mv = ((const float4*)nms)[c4];
    v.x = wv.x * (v.x - mv.x * mn.x) * iv.x + bv.x;
    v.y = wv.y * (v.y - mv.y * mn.y) * iv.y + bv.y;
    v.z = wv.z * (v.z - mv.z * mn.z) * iv.z + bv.z;
    v.w = wv.w * (v.w - mv.w * mn.w) * iv.w + bv.w;
    ((float4*)g_bufX)[i] = v;
}

// ---------------- global max pool: grid (G, 4) ----------------
__global__ void k_pool() {
    __shared__ float sh[256];
    int g = blockIdx.x, q = blockIdx.y;
    int tc = threadIdx.x & 31, tr = threadIdx.x >> 5;
    int c = q * 32 + tc;
    int s0 = g_start[g], s1 = g_start[g + 1];
    float m = __int_as_float(0xff800000u);
    for (int r = s0 + tr; r < s1; r += 8)
        m = fmaxf(m, g_bufX[r * CATC + c]);
    sh[threadIdx.x] = m;
    __syncthreads();
    for (int off = 128; off >= 32; off >>= 1) {
        if (threadIdx.x < off) sh[threadIdx.x] = fmaxf(sh[threadIdx.x], sh[threadIdx.x + off]);
        __syncthreads();
    }
    if (threadIdx.x < 32) g_pool[g * CATC + c] = sh[tc];
}

// ---------------- final fc ----------------
__global__ void k_fc(const float* __restrict__ fw, const float* __restrict__ fb,
                     float* __restrict__ out) {
    int g = blockIdx.x, o = threadIdx.x;
    float acc = fb[o];
#pragma unroll
    for (int c = 0; c < CATC; c += 4) {
        float4 p  = *(const float4*)&g_pool[g * CATC + c];
        float4 wv = *(const float4*)&fw[o * CATC + c];
        acc += p.x * wv.x + p.y * wv.y + p.z * wv.z + p.w * wv.w;
    }
    out[g * OUTD + o] = acc;
}

// ---------------- launch ----------------
extern "C" void kernel_launch(void* const* d_in, const int* in_sizes, int n_in,
                              void* d_out, int out_size) {
    const float* x     = (const float*)d_in[0];
    const int*   ei    = (const int*)d_in[1];
    const int*   batch = (const int*)d_in[2];
    const float* enc_w = (const float*)d_in[3];
    const float* enc_b = (const float*)d_in[4];
    const float* w1    = (const float*)d_in[5];
    const float* as1   = (const float*)d_in[6];
    const float* ad1   = (const float*)d_in[7];
    const float* b1    = (const float*)d_in[8];
    const float* n1w   = (const float*)d_in[9];
    const float* n1b   = (const float*)d_in[10];
    const float* n1ms  = (const float*)d_in[11];
    const float* w2    = (const float*)d_in[12];
    const float* as2   = (const float*)d_in[13];
    const float* ad2   = (const float*)d_in[14];
    const float* b2    = (const float*)d_in[15];
    const float* n2w   = (const float*)d_in[16];
    const float* n2b   = (const float*)d_in[17];
    const float* n2ms  = (const float*)d_in[18];
    const float* fw    = (const float*)d_in[19];
    const float* fb    = (const float*)d_in[20];
    float* out = (float*)d_out;

    cudaFuncSetAttribute(k_gemm<0, 0, true, false>,
                         cudaFuncAttributeMaxDynamicSharedMemorySize, GEMM_SMEM);
    cudaFuncSetAttribute(k_gemm<1, 1, false, true>,
                         cudaFuncAttributeMaxDynamicSharedMemorySize, GEMM_SMEM);

    const int gemmBlocks = (NN + 127) / 128;
    const int elemBlocks = (NN * 32 + 255) / 256;
    const int gatBlocks  = (NN * 32 + 255) / 256;
    const int edgeBlocks = (NE + 255) / 256;

    // segment offsets + CSR build (shared by both layers)
    k_start_init<<<1, NG + 1>>>();
    k_start_fill<<<(NN + 255) / 256, 256>>>(batch);
    k_cnt_zero<<<(NN + 255) / 256, 256>>>();
    k_deg<<<edgeBlocks, 256>>>(ei);
    k_scan1<<<SCAN_B, 256>>>();
    k_scan2<<<1, 1>>>();
    k_scan3<<<(NN + 255) / 256, 256>>>();
    k_fill<<<edgeBlocks, 256>>>(ei);

    // encoder
    k_gemm<0, 0, true, false><<<gemmBlocks, 256, GEMM_SMEM>>>(x, enc_w, enc_b, nullptr, nullptr);

    // ---- layer 1 ----
    k_gemm<1, 1, false, true><<<gemmBlocks, 256, GEMM_SMEM>>>(nullptr, w1, nullptr, as1, ad1);
    k_shift_init<<<1, 32>>>();
    k_shift<<<296, 256>>>();
    k_gat<<<gatBlocks, 256>>>(b1);
    k_norm_stats<<<dim3(NG, 4), 256>>>(n1ms);
    k_norm_apply<<<elemBlocks, 256>>>(batch, n1w, n1b, n1ms);

    // ---- layer 2 ----
    k_gemm<1, 1, false, true><<<gemmBlocks, 256, GEMM_SMEM>>>(nullptr, w2, nullptr, as2, ad2);
    k_shift_init<<<1, 32>>>();
    k_shift<<<296, 256>>>();
    k_gat<<<gatBlocks, 256>>>(b2);
    k_norm_stats<<<dim3(NG, 4), 256>>>(n2ms);
    k_norm_apply<<<elemBlocks, 256>>>(batch, n2w, n2b, n2ms);

    // ---- pool + fc ----
    k_pool<<<dim3(NG, 4), 256>>>();
    k_fc<<<NG, OUTD>>>(fw, fb, out);
}